// round 3
// baseline (speedup 1.0000x reference)
#include <cuda_runtime.h>
#include <cstdint>
#include <cfloat>

#define BN_EPS 1e-5f

// ======================= device global scratch =======================
__device__ float g_psum[32768];
__device__ float g_psq[32768];
__device__ double g_dsum[512], g_dsq[512];

__device__ float g_t_in[3];   __device__ int g_f_in[3];
__device__ float g_t1[128];   __device__ int g_f1[128];
__device__ float g_t2[256];   __device__ int g_f2[256];
__device__ float g_t3[18432]; __device__ int g_f3[18432];
__device__ float g_t4[1024];  __device__ int g_f4[1024];

__device__ unsigned g_W1m[128];
__device__ uint4    g_W2p[256 * 9];
__device__ uint4    g_W3p[512 * 9 * 2];
__device__ unsigned g_FW0pT[576 * 1024];
__device__ unsigned g_FW1p[10 * 32];

__device__ signed char g_a1[128 * 31 * 31 * 128];  // pooled conv1 ints, NHWC
__device__ uint4       g_P1[128 * 31 * 31];        // packed signs, 128 bits/pixel
__device__ short       g_a2[128 * 14 * 14 * 256];  // pooled conv2 ints, NHWC
__device__ uint4       g_P2[128 * 14 * 14 * 2];    // packed signs, 256 bits/pixel
__device__ short       g_p3[128 * 18432];          // pooled conv3 ints, NCHW-flat
__device__ unsigned    g_P3[128 * 576];            // packed signs (ternary: sign plane)
__device__ unsigned    g_P3nz[128 * 576];          // ternary: nonzero mask
__device__ short       g_b1[128 * 1024];           // fc1 ints
__device__ unsigned    g_P4[128 * 32];             // packed signs
__device__ unsigned    g_P4nz[128 * 32];           // nonzero mask

// ======================= helpers =======================
__device__ __forceinline__ int popc4(uint4 a, uint4 b) {
    return __popc(a.x ^ b.x) + __popc(a.y ^ b.y) + __popc(a.z ^ b.z) + __popc(a.w ^ b.w);
}

__device__ __forceinline__ void bn_thresh(float s, float q, float N,
                                          float g, float b, float* t, int* f) {
    float m = s / N;
    float v = q / N - m * m;
    v = fmaxf(v, 0.0f);
    if (g != 0.0f) {
        *t = m - b * sqrtf(v + BN_EPS) / g;
        *f = (g < 0.0f) ? 1 : 0;
    } else {
        *t = (b > 0.0f) ? -FLT_MAX : FLT_MAX;
        *f = 0;
    }
}

__device__ __forceinline__ float preluf(float v, float a) {
    return v >= 0.0f ? v : a * v;
}

// ======================= layer 0: input BN stats (fp64) =======================
__global__ void k_stats_x(const float* __restrict__ x) {
    __shared__ double ss[256], sq[256];
    int n = blockIdx.x, c = blockIdx.y, t = threadIdx.x;
    const float* p = x + (n * 3 + c) * 4096;
    double s = 0., q = 0.;
    for (int i = t; i < 4096; i += 256) {
        double v = (double)p[i];
        s += v; q += v * v;
    }
    ss[t] = s; sq[t] = q;
    __syncthreads();
    for (int o = 128; o > 0; o >>= 1) {
        if (t < o) { ss[t] += ss[t + o]; sq[t] += sq[t + o]; }
        __syncthreads();
    }
    if (t == 0) { g_dsum[c * 128 + n] = ss[0]; g_dsq[c * 128 + n] = sq[0]; }
}

__global__ void k_fin_in(const float* __restrict__ gma, const float* __restrict__ bta) {
    int c = threadIdx.x;  // 3 threads
    double s = 0., q = 0.;
    for (int b = 0; b < 128; b++) { s += g_dsum[c * 128 + b]; q += g_dsq[c * 128 + b]; }
    double N = 524288.0;
    double m = s / N;
    double v = q / N - m * m;
    if (v < 0.) v = 0.;
    float g = gma[c], b = bta[c];
    if (g != 0.0f) {
        g_t_in[c] = (float)(m - (double)b * sqrt(v + (double)BN_EPS) / (double)g);
        g_f_in[c] = (g < 0.0f) ? 1 : 0;
    } else {
        g_t_in[c] = (b > 0.0f) ? -FLT_MAX : FLT_MAX;
        g_f_in[c] = 0;
    }
}

// ======================= weight packing =======================
__global__ void k_pack_w1(const float* __restrict__ w) {  // [128,3,3,3]
    int oc = threadIdx.x;
    unsigned m = 0;
    for (int c = 0; c < 3; c++)
        for (int ky = 0; ky < 3; ky++)
            for (int kx = 0; kx < 3; kx++)
                if (w[((oc * 3 + c) * 3 + ky) * 3 + kx] > 0.f)
                    m |= 1u << (c * 9 + ky * 3 + kx);
    g_W1m[oc] = m;
}

__global__ void k_pack_w2(const float* __restrict__ w) {  // [256,128,3,3]
    int tap = blockIdx.x;              // 0..8
    int oc = threadIdx.x;              // 0..255
    int ky = tap / 3, kx = tap % 3;
    unsigned v[4] = {0, 0, 0, 0};
    for (int c = 0; c < 128; c++)
        if (w[((oc * 128 + c) * 3 + ky) * 3 + kx] > 0.f) v[c >> 5] |= 1u << (c & 31);
    g_W2p[oc * 9 + tap] = make_uint4(v[0], v[1], v[2], v[3]);
}

__global__ void k_pack_w3(const float* __restrict__ w) {  // [512,256,3,3]
    int tap = blockIdx.x;                       // 0..8
    int oc = blockIdx.y * 256 + threadIdx.x;    // 0..511
    int ky = tap / 3, kx = tap % 3;
    for (int h = 0; h < 2; h++) {
        unsigned v[4] = {0, 0, 0, 0};
        for (int i = 0; i < 128; i++) {
            int c = h * 128 + i;
            if (w[((oc * 256 + c) * 3 + ky) * 3 + kx] > 0.f) v[i >> 5] |= 1u << (i & 31);
        }
        g_W3p[(oc * 9 + tap) * 2 + h] = make_uint4(v[0], v[1], v[2], v[3]);
    }
}

__global__ void k_pack_fw0(const float* __restrict__ fw) {  // [1024,18432] -> [w][j]
    int id = blockIdx.x * 256 + threadIdx.x;   // < 589824
    int j = id / 576, w = id % 576;
    const float* src = fw + j * 18432 + w * 32;
    unsigned v = 0;
#pragma unroll
    for (int i = 0; i < 32; i++)
        if (src[i] > 0.f) v |= 1u << i;
    g_FW0pT[w * 1024 + j] = v;
}

__global__ void k_pack_fw1(const float* __restrict__ fw) {  // [10,1024]
    int id = threadIdx.x;  // 320 threads
    int k = id / 32, w = id % 32;
    const float* src = fw + k * 1024 + w * 32;
    unsigned v = 0;
#pragma unroll
    for (int i = 0; i < 32; i++)
        if (src[i] > 0.f) v |= 1u << i;
    g_FW1p[k * 32 + w] = v;
}

// ======================= conv1 (3->128, 64->62, pool->31) =======================
__global__ void __launch_bounds__(128) k_conv1(const float* __restrict__ x) {
    __shared__ unsigned sW[128];
    int tid = threadIdx.x;
    sW[tid] = g_W1m[tid];
    __syncthreads();
    int idx = blockIdx.x * 128 + tid;           // < 123008
    int n = idx / 961, r = idx % 961, py = r / 31, px = r % 31;
    float tc[3] = {g_t_in[0], g_t_in[1], g_t_in[2]};
    int fc[3] = {g_f_in[0], g_f_in[1], g_f_in[2]};

    unsigned m[4] = {0, 0, 0, 0};
#pragma unroll
    for (int c = 0; c < 3; c++) {
        const float* xp = x + ((n * 3 + c) * 64 + 2 * py) * 64 + 2 * px;
#pragma unroll
        for (int rr = 0; rr < 4; rr++) {
#pragma unroll
            for (int cc = 0; cc < 4; cc++) {
                unsigned b = ((xp[rr * 64 + cc] > tc[c]) != (fc[c] != 0)) ? 1u : 0u;
#pragma unroll
                for (int dy = 0; dy < 2; dy++) {
#pragma unroll
                    for (int dx = 0; dx < 2; dx++) {
                        int ky = rr - dy, kx = cc - dx;
                        if (ky >= 0 && ky < 3 && kx >= 0 && kx < 3)
                            m[dy * 2 + dx] |= b << (c * 9 + ky * 3 + kx);
                    }
                }
            }
        }
    }
    unsigned* outw = reinterpret_cast<unsigned*>(g_a1) + (size_t)idx * 32;
#pragma unroll 4
    for (int oc4 = 0; oc4 < 32; oc4++) {
        unsigned pk = 0;
#pragma unroll
        for (int s = 0; s < 4; s++) {
            unsigned wv = sW[oc4 * 4 + s];
            int p0 = __popc(m[0] ^ wv), p1 = __popc(m[1] ^ wv);
            int p2 = __popc(m[2] ^ wv), p3 = __popc(m[3] ^ wv);
            int mn = min(min(p0, p1), min(p2, p3));
            int p = 27 - 2 * mn;  // pooled pre-activation, odd, |p|<=27
            pk |= ((unsigned)(unsigned char)(signed char)p) << (8 * s);
        }
        outw[oc4] = pk;
    }
}

// ======================= stats over a1 (128ch x 123008) =======================
__global__ void k_stats1(const float* __restrict__ cp0) {
    __shared__ float ss[256], sq[256];
    int t = threadIdx.x, b = blockIdx.x;
    int c = t & 127, h = t >> 7;
    float a = cp0[0];
    float s = 0.f, q = 0.f;
    for (int i = h; i < 961; i += 2) {
        int pixel = b * 961 + i;
        float v = (float)g_a1[(size_t)pixel * 128 + c];
        v = preluf(v, a);
        s += v; q += v * v;
    }
    ss[t] = s; sq[t] = q;
    __syncthreads();
    if (t < 128) {
        g_psum[b * 128 + t] = ss[t] + ss[t + 128];
        g_psq[b * 128 + t] = sq[t] + sq[t + 128];
    }
}

__global__ void k_fin1(const float* __restrict__ gma, const float* __restrict__ bta) {
    int c = threadIdx.x;  // 128
    float s = 0.f, q = 0.f;
    for (int b = 0; b < 128; b++) { s += g_psum[b * 128 + c]; q += g_psq[b * 128 + c]; }
    bn_thresh(s, q, 123008.f, gma[c], bta[c], &g_t1[c], &g_f1[c]);
}

// ======================= pack a1 -> P1 =======================
__global__ void k_pack1(const float* __restrict__ cp0) {
    __shared__ float st[128];
    __shared__ int sf[128];
    int tid = threadIdx.x;
    st[tid] = g_t1[tid]; sf[tid] = g_f1[tid];
    __syncthreads();
    int pixel = blockIdx.x * 128 + tid;  // < 123008
    float a = cp0[0];
    const int* src = reinterpret_cast<const int*>(g_a1) + (size_t)pixel * 32;
    unsigned w[4];
#pragma unroll
    for (int j = 0; j < 4; j++) {
        unsigned wd = 0;
#pragma unroll
        for (int i = 0; i < 32; i++) {
            int c = j * 32 + i;
            int word = src[c >> 2];
            float v = (float)((signed char)((word >> (8 * (c & 3))) & 0xFF));
            v = preluf(v, a);
            wd |= ((v > st[c]) != (sf[c] != 0)) ? (1u << i) : 0u;
        }
        w[j] = wd;
    }
    g_P1[pixel] = make_uint4(w[0], w[1], w[2], w[3]);
}

// ======================= conv2 (128->256, 31->29, pool->14) =======================
__global__ void __launch_bounds__(256) k_conv2() {
    __shared__ uint4 sIn[4][31];
    int py = blockIdx.x, n = blockIdx.y, oc = threadIdx.x;
    if (oc < 124) {
        int r = oc / 31, cc = oc % 31;
        sIn[r][cc] = g_P1[(n * 31 + 2 * py + r) * 31 + cc];
    }
    uint4 w[9];
#pragma unroll
    for (int k = 0; k < 9; k++) w[k] = g_W2p[oc * 9 + k];
    __syncthreads();
    short* op = g_a2 + (size_t)((n * 14 + py) * 14) * 256 + oc;
    for (int px = 0; px < 14; px++) {
        int base = 2 * px;
        int best = 1 << 30;
#pragma unroll
        for (int dy = 0; dy < 2; dy++) {
#pragma unroll
            for (int dx = 0; dx < 2; dx++) {
                int acc = 0;
#pragma unroll
                for (int ky = 0; ky < 3; ky++)
#pragma unroll
                    for (int kx = 0; kx < 3; kx++)
                        acc += popc4(sIn[dy + ky][base + dx + kx], w[ky * 3 + kx]);
                best = min(best, acc);
            }
        }
        op[px * 256] = (short)(1152 - 2 * best);
    }
}

// ======================= stats over a2 (256ch x 25088) =======================
__global__ void k_stats2(const float* __restrict__ cp1) {
    int c = threadIdx.x, b = blockIdx.x;  // 256 threads, 128 blocks
    float a = cp1[0];
    float s = 0.f, q = 0.f;
    for (int i = 0; i < 196; i++) {
        int pixel = b * 196 + i;
        float v = (float)g_a2[(size_t)pixel * 256 + c];
        v = preluf(v, a);
        s += v; q += v * v;
    }
    g_psum[b * 256 + c] = s;
    g_psq[b * 256 + c] = q;
}

__global__ void k_fin2(const float* __restrict__ gma, const float* __restrict__ bta) {
    int c = threadIdx.x;  // 256
    float s = 0.f, q = 0.f;
    for (int b = 0; b < 128; b++) { s += g_psum[b * 256 + c]; q += g_psq[b * 256 + c]; }
    bn_thresh(s, q, 25088.f, gma[c], bta[c], &g_t2[c], &g_f2[c]);
}

// ======================= pack a2 -> P2 =======================
__global__ void k_pack2(const float* __restrict__ cp1) {
    __shared__ float st[256];
    __shared__ int sf[256];
    int tid = threadIdx.x;
    st[tid] = g_t2[tid]; sf[tid] = g_f2[tid];
    __syncthreads();
    int pixel = blockIdx.x * 256 + tid;  // < 25088
    float a = cp1[0];
    const short* src = g_a2 + (size_t)pixel * 256;
    unsigned wd[8];
#pragma unroll
    for (int j = 0; j < 8; j++) {
        unsigned v = 0;
#pragma unroll
        for (int i = 0; i < 32; i++) {
            int c = j * 32 + i;
            float val = (float)src[c];
            val = preluf(val, a);
            v |= ((val > st[c]) != (sf[c] != 0)) ? (1u << i) : 0u;
        }
        wd[j] = v;
    }
    g_P2[pixel * 2] = make_uint4(wd[0], wd[1], wd[2], wd[3]);
    g_P2[pixel * 2 + 1] = make_uint4(wd[4], wd[5], wd[6], wd[7]);
}

// ======================= conv3 (256->512, 14->12, pool->6) =======================
__global__ void __launch_bounds__(256) k_conv3() {
    __shared__ uint4 sIn[4][14][2];
    int py = blockIdx.x, n = blockIdx.y;
    int oc = blockIdx.z * 256 + threadIdx.x;
    // 4 rows x 14 cols x 2 halves = 112 uint4 entries
    for (int i = threadIdx.x; i < 112; i += 256) {
        int h = i & 1, t_ = i >> 1;
        int r = t_ / 14, cc = t_ % 14;
        sIn[r][cc][h] = g_P2[((n * 14 + 2 * py + r) * 14 + cc) * 2 + h];
    }
    uint4 w[18];
#pragma unroll
    for (int k = 0; k < 18; k++) w[k] = g_W3p[oc * 18 + k];
    __syncthreads();
    short* op = g_p3 + (size_t)n * 18432 + oc * 36 + py * 6;
    for (int px = 0; px < 6; px++) {
        int base = 2 * px;
        int best = 1 << 30;
#pragma unroll
        for (int dy = 0; dy < 2; dy++) {
#pragma unroll
            for (int dx = 0; dx < 2; dx++) {
                int acc = 0;
#pragma unroll
                for (int ky = 0; ky < 3; ky++)
#pragma unroll
                    for (int kx = 0; kx < 3; kx++) {
                        acc += popc4(sIn[dy + ky][base + dx + kx][0], w[(ky * 3 + kx) * 2]);
                        acc += popc4(sIn[dy + ky][base + dx + kx][1], w[(ky * 3 + kx) * 2 + 1]);
                    }
                best = min(best, acc);
            }
        }
        op[px] = (short)(2304 - 2 * best);
    }
}

// ======================= BN1d stats over p3 (18432 features x 128 samples) ===
__global__ void k_stats3(const float* __restrict__ cp2,
                         const float* __restrict__ fg, const float* __restrict__ fb) {
    int f = blockIdx.x * 256 + threadIdx.x;  // < 18432
    float a = cp2[0];
    float s = 0.f, q = 0.f;
    for (int n = 0; n < 128; n++) {
        float v = (float)g_p3[(size_t)n * 18432 + f];
        v = preluf(v, a);
        s += v; q += v * v;
    }
    bn_thresh(s, q, 128.f, fg[f], fb[f], &g_t3[f], &g_f3[f]);
}

// pack with TERNARY semantics: tie (val == t) -> sign 0 (nz bit cleared)
__global__ void k_pack3(const float* __restrict__ cp2) {
    int id = blockIdx.x * 256 + threadIdx.x;  // < 73728
    int n = id / 576, w = id % 576;
    float a = cp2[0];
    const short* src = g_p3 + (size_t)n * 18432 + w * 32;
    unsigned v = 0, nz = 0;
#pragma unroll
    for (int i = 0; i < 32; i++) {
        float val = (float)src[i];
        val = preluf(val, a);
        float t = g_t3[w * 32 + i];
        if (val != t) {
            nz |= 1u << i;
            if ((val > t) != (g_f3[w * 32 + i] != 0)) v |= 1u << i;
        }
    }
    g_P3[n * 576 + w] = v;
    g_P3nz[n * 576 + w] = nz;
}

// ======================= FC1 (18432 -> 1024), ternary-aware =======================
__global__ void __launch_bounds__(1024) k_fc1() {
    __shared__ unsigned sA[576], sB[576], sAnz[576], sBnz[576];
    __shared__ int sKA, sKB;
    int n0 = blockIdx.x * 2, j = threadIdx.x;
    if (j == 0) { sKA = 0; sKB = 0; }
    __syncthreads();
    if (j < 576) {
        unsigned a = g_P3[n0 * 576 + j];
        unsigned b = g_P3[(n0 + 1) * 576 + j];
        unsigned an = g_P3nz[n0 * 576 + j];
        unsigned bn = g_P3nz[(n0 + 1) * 576 + j];
        sA[j] = a; sB[j] = b; sAnz[j] = an; sBnz[j] = bn;
        atomicAdd(&sKA, __popc(an));
        atomicAdd(&sKB, __popc(bn));
    }
    __syncthreads();
    int a0 = 0, a1 = 0;
#pragma unroll 8
    for (int w = 0; w < 576; w++) {
        unsigned wt = g_FW0pT[w * 1024 + j];
        a0 += __popc((sA[w] ^ wt) & sAnz[w]);
        a1 += __popc((sB[w] ^ wt) & sBnz[w]);
    }
    g_b1[n0 * 1024 + j] = (short)(sKA - 2 * a0);
    g_b1[(n0 + 1) * 1024 + j] = (short)(sKB - 2 * a1);
}

// ======================= BN1d stats over b1 (1024 x 128) =======================
__global__ void k_stats4(const float* __restrict__ fp0,
                         const float* __restrict__ fg, const float* __restrict__ fb) {
    int f = blockIdx.x * 256 + threadIdx.x;  // < 1024
    float a = fp0[0];
    float s = 0.f, q = 0.f;
    for (int n = 0; n < 128; n++) {
        float v = (float)g_b1[n * 1024 + f];
        v = preluf(v, a);
        s += v; q += v * v;
    }
    bn_thresh(s, q, 128.f, fg[f], fb[f], &g_t4[f], &g_f4[f]);
}

__global__ void k_pack4(const float* __restrict__ fp0) {
    int id = blockIdx.x * 256 + threadIdx.x;  // < 4096
    int n = id / 32, w = id % 32;
    float a = fp0[0];
    unsigned v = 0, nz = 0;
#pragma unroll
    for (int i = 0; i < 32; i++) {
        float val = (float)g_b1[n * 1024 + w * 32 + i];
        val = preluf(val, a);
        float t = g_t4[w * 32 + i];
        if (val != t) {
            nz |= 1u << i;
            if ((val > t) != (g_f4[w * 32 + i] != 0)) v |= 1u << i;
        }
    }
    g_P4[n * 32 + w] = v;
    g_P4nz[n * 32 + w] = nz;
}

// ======================= FC2 (1024 -> 10) + prelu + scale =======================
__global__ void k_fc2(const float* __restrict__ fp1, const float* __restrict__ scale,
                      float* __restrict__ out) {
    int idx = blockIdx.x * 256 + threadIdx.x;
    if (idx >= 1280) return;
    int n = idx / 10, k = idx % 10;
    int acc = 0, knz = 0;
#pragma unroll
    for (int w = 0; w < 32; w++) {
        unsigned nz = g_P4nz[n * 32 + w];
        knz += __popc(nz);
        acc += __popc((g_P4[n * 32 + w] ^ g_FW1p[k * 32 + w]) & nz);
    }
    float v = (float)(knz - 2 * acc);
    v = preluf(v, fp1[0]);
    out[n * 10 + k] = v * scale[0];
}

// ======================= launch =======================
extern "C" void kernel_launch(void* const* d_in, const int* in_sizes, int n_in,
                              void* d_out, int out_size) {
    const float* x   = (const float*)d_in[0];
    const float* cg0 = (const float*)d_in[1];
    const float* cb0 = (const float*)d_in[2];
    const float* cw0 = (const float*)d_in[3];
    const float* cp0 = (const float*)d_in[4];
    const float* cg1 = (const float*)d_in[5];
    const float* cb1 = (const float*)d_in[6];
    const float* cw1 = (const float*)d_in[7];
    const float* cp1 = (const float*)d_in[8];
    const float* cg2 = (const float*)d_in[9];
    const float* cb2 = (const float*)d_in[10];
    const float* cw2 = (const float*)d_in[11];
    const float* cp2 = (const float*)d_in[12];
    const float* fg0 = (const float*)d_in[13];
    const float* fb0 = (const float*)d_in[14];
    const float* fw0 = (const float*)d_in[15];
    const float* fp0 = (const float*)d_in[16];
    const float* fg1 = (const float*)d_in[17];
    const float* fb1 = (const float*)d_in[18];
    const float* fw1 = (const float*)d_in[19];
    const float* fp1 = (const float*)d_in[20];
    const float* scl = (const float*)d_in[21];
    float* out = (float*)d_out;

    // Layer 1
    k_stats_x<<<dim3(128, 3), 256>>>(x);
    k_fin_in<<<1, 3>>>(cg0, cb0);
    k_pack_w1<<<1, 128>>>(cw0);
    k_conv1<<<961, 128>>>(x);

    // Layer 2
    k_stats1<<<128, 256>>>(cp0);
    k_fin1<<<1, 128>>>(cg1, cb1);
    k_pack1<<<961, 128>>>(cp0);
    k_pack_w2<<<9, 256>>>(cw1);
    k_conv2<<<dim3(14, 128), 256>>>();

    // Layer 3
    k_stats2<<<128, 256>>>(cp1);
    k_fin2<<<1, 256>>>(cg2, cb2);
    k_pack2<<<98, 256>>>(cp1);
    k_pack_w3<<<dim3(9, 2), 256>>>(cw2);
    k_conv3<<<dim3(6, 128, 2), 256>>>();

    // FC1
    k_stats3<<<72, 256>>>(cp2, fg0, fb0);
    k_pack3<<<288, 256>>>(cp2);
    k_pack_fw0<<<2304, 256>>>(fw0);
    k_fc1<<<64, 1024>>>();

    // FC2
    k_stats4<<<4, 256>>>(fp0, fg1, fb1);
    k_pack4<<<16, 256>>>(fp0);
    k_pack_fw1<<<1, 320>>>(fw1);
    k_fc2<<<5, 256>>>(fp1, scl, out);
}